// round 4
// baseline (speedup 1.0000x reference)
#include <cuda_runtime.h>
#include <math.h>
#include <stdint.h>

#define BATCH  8
#define SEQ    577
#define SEQP   608          // padded score row stride (multiple of 32)
#define DIM    768
#define HEADS  12
#define HDIM   64
#define MLPD   3072
#define DEPTH  8
#define NPATCH 576
#define PDIM   768
#define IMGH   384
#define PSZ    16
#define HP     24

// ---------------- scratch (device globals; allocation is banned) ------------
__device__ float g_X  [BATCH * SEQ * DIM];
__device__ float g_Y  [BATCH * SEQ * DIM];
__device__ float g_QKV[BATCH * SEQ * 3 * DIM + 64 * 3 * DIM]; // tail pad: PV K overrun reads
__device__ float g_S  [BATCH * HEADS * SEQ * SEQP];
__device__ float g_O  [BATCH * SEQ * DIM];
__device__ float g_H  [BATCH * SEQ * MLPD];
__device__ float g_P  [BATCH * NPATCH * PDIM];

// ---------------- tf32 / cp.async helpers ------------------------------------
__device__ __forceinline__ unsigned f2tf(float f) {
    unsigned u;
    asm("cvt.rna.tf32.f32 %0, %1;" : "=r"(u) : "f"(f));
    return u;
}

__device__ __forceinline__ void cpa16(uint32_t saddr, const float* gptr, bool pred) {
    int sz = pred ? 16 : 0;
    asm volatile("cp.async.cg.shared.global [%0], [%1], 16, %2;\n"
                 :: "r"(saddr), "l"(gptr), "r"(sz));
}
#define CP_COMMIT() asm volatile("cp.async.commit_group;\n" ::: "memory")
#define CP_WAIT0()  asm volatile("cp.async.wait_group 0;\n" ::: "memory")

#define MMA_TF32(d, a, b)                                                     \
    asm volatile("mma.sync.aligned.m16n8k8.row.col.f32.tf32.tf32.f32 "        \
                 "{%0,%1,%2,%3}, {%4,%5,%6,%7}, {%8,%9}, {%0,%1,%2,%3};\n"    \
                 : "+f"(d[0]), "+f"(d[1]), "+f"(d[2]), "+f"(d[3])             \
                 : "r"(a[0]), "r"(a[1]), "r"(a[2]), "r"(a[3]),                \
                   "r"(b[0]), "r"(b[1]))

// ---------------- cp.async double-buffered tf32 GEMM --------------------------
// C[z] = op( A[z] @ B[z] (+ bias) ), fuse: 0=none, 1=gelu(exact), 2=residual
// Requirements (all call sites satisfy): K % BK == 0, all pointers/lds 16B-
// aligned, N edge only when TRANSB (row-predicated zfill).
template<int BM, int BN, int BK, int WM, int WN, bool TRANSB>
__global__ void __launch_bounds__(WM * WN * 32)
gemm_tc(const float* __restrict__ A, int lda, long long sAb, long long sAh,
        const float* __restrict__ Bm, int ldb, long long sBb, long long sBh,
        const float* __restrict__ bias,
        float* __restrict__ C, int ldc, long long sCb, long long sCh,
        int M, int N, int K, int fuse)
{
    constexpr int NTHREADS = WM * WN * 32;
    constexpr int MT = (BM / WM) / 16;
    constexpr int NT = (BN / WN) / 8;
    constexpr int A_IT = BM * BK / (NTHREADS * 4);
    constexpr int B_IT = TRANSB ? (BN * BK / (NTHREADS * 4)) : (BK * BN / (NTHREADS * 4));
    constexpr int ASTRIDE = BK + 4;                 // words; conflict-free
    constexpr int BSTRIDE = TRANSB ? (BK + 4) : (BN + 4);
    constexpr int ASZ = BM * ASTRIDE;
    constexpr int BSZ = TRANSB ? BN * BSTRIDE : BK * BSTRIDE;

    extern __shared__ float smem[];
    float* sA[2] = { smem, smem + ASZ };
    float* sB[2] = { smem + 2 * ASZ, smem + 2 * ASZ + BSZ };

    int z  = blockIdx.z;
    int zb = z / HEADS, zh = z % HEADS;
    A  += zb * sAb + zh * sAh;
    Bm += zb * sBb + zh * sBh;
    C  += zb * sCb + zh * sCh;

    int r0 = blockIdx.y * BM;
    int c0 = blockIdx.x * BN;
    int tid  = threadIdx.x;
    int wid  = tid >> 5, lane = tid & 31;
    int wm   = wid / WN, wn = wid % WN;
    int q    = lane >> 2, r = lane & 3;

    float acc[MT][NT][4];
    #pragma unroll
    for (int i = 0; i < MT; i++)
        #pragma unroll
        for (int j = 0; j < NT; j++)
            #pragma unroll
            for (int t = 0; t < 4; t++) acc[i][j][t] = 0.f;

    uint32_t sAaddr[2], sBaddr[2];
    #pragma unroll
    for (int b = 0; b < 2; b++) {
        sAaddr[b] = (uint32_t)__cvta_generic_to_shared(sA[b]);
        sBaddr[b] = (uint32_t)__cvta_generic_to_shared(sB[b]);
    }

    auto loadTile = [&](int k0, int buf) {
        // A tile: BM x BK, row-predicated
        #pragma unroll
        for (int it = 0; it < A_IT; it++) {
            int idx = (tid + it * NTHREADS) * 4;
            int m = idx / BK, kk = idx % BK;
            bool p = (r0 + m) < M;
            int row = p ? (r0 + m) : 0;
            cpa16(sAaddr[buf] + (m * ASTRIDE + kk) * 4,
                  A + (long long)row * lda + k0 + kk, p);
        }
        if (TRANSB) {
            // B global [N,K] -> sB[n][k], row(n)-predicated
            #pragma unroll
            for (int it = 0; it < B_IT; it++) {
                int idx = (tid + it * NTHREADS) * 4;
                int n = idx / BK, kk = idx % BK;
                bool p = (c0 + n) < N;
                int row = p ? (c0 + n) : 0;
                cpa16(sBaddr[buf] + (n * BSTRIDE + kk) * 4,
                      Bm + (long long)row * ldb + k0 + kk, p);
            }
        } else {
            // B global [K,N] -> sB[k][n], no predicates (K,N tile-exact)
            #pragma unroll
            for (int it = 0; it < B_IT; it++) {
                int idx = (tid + it * NTHREADS) * 4;
                int kk = idx / BN, n = idx % BN;
                cpa16(sBaddr[buf] + (kk * BSTRIDE + n) * 4,
                      Bm + (long long)(k0 + kk) * ldb + c0 + n, true);
            }
        }
        CP_COMMIT();
    };

    int T = K / BK;
    loadTile(0, 0);

    for (int t = 0; t < T; t++) {
        CP_WAIT0();
        __syncthreads();
        if (t + 1 < T) loadTile((t + 1) * BK, (t + 1) & 1);
        const float* cA = sA[t & 1];
        const float* cB = sB[t & 1];

        #pragma unroll
        for (int kk = 0; kk < BK; kk += 8) {
            unsigned af[MT][4];
            unsigned bf[NT][2];
            #pragma unroll
            for (int i = 0; i < MT; i++) {
                int m = wm * (BM / WM) + i * 16;
                af[i][0] = f2tf(cA[(m + q    ) * ASTRIDE + kk + r    ]);
                af[i][1] = f2tf(cA[(m + q + 8) * ASTRIDE + kk + r    ]);
                af[i][2] = f2tf(cA[(m + q    ) * ASTRIDE + kk + r + 4]);
                af[i][3] = f2tf(cA[(m + q + 8) * ASTRIDE + kk + r + 4]);
            }
            #pragma unroll
            for (int j = 0; j < NT; j++) {
                int n = wn * (BN / WN) + j * 8;
                if (TRANSB) {
                    bf[j][0] = f2tf(cB[(n + q) * BSTRIDE + kk + r    ]);
                    bf[j][1] = f2tf(cB[(n + q) * BSTRIDE + kk + r + 4]);
                } else {
                    bf[j][0] = f2tf(cB[(kk + r    ) * BSTRIDE + n + q]);
                    bf[j][1] = f2tf(cB[(kk + r + 4) * BSTRIDE + n + q]);
                }
            }
            #pragma unroll
            for (int i = 0; i < MT; i++)
                #pragma unroll
                for (int j = 0; j < NT; j++)
                    MMA_TF32(acc[i][j], af[i], bf[j]);
        }
        __syncthreads();
    }

    // ---- epilogue ----
    #pragma unroll
    for (int i = 0; i < MT; i++) {
        #pragma unroll
        for (int j = 0; j < NT; j++) {
            #pragma unroll
            for (int t = 0; t < 4; t++) {
                int row = r0 + wm * (BM / WM) + i * 16 + q + ((t >= 2) ? 8 : 0);
                int col = c0 + wn * (BN / WN) + j * 8 + r * 2 + (t & 1);
                if (row >= M || col >= N) continue;
                float v = acc[i][j][t];
                if (bias) v += bias[col];
                if (fuse == 1) v = 0.5f * v * (1.f + erff(v * 0.70710678118654752f));
                long long off = (long long)row * ldc + col;
                if (fuse == 2) v += C[off];
                C[off] = v;
            }
        }
    }
}

// ---------------- reductions -------------------------------------------------
__device__ __forceinline__ float blockReduceSum(float v, volatile float* sh) {
    int lane = threadIdx.x & 31, w = threadIdx.x >> 5;
    #pragma unroll
    for (int o = 16; o; o >>= 1) v += __shfl_down_sync(0xffffffffu, v, o);
    if (lane == 0) sh[w] = v;
    __syncthreads();
    if (threadIdx.x < 32) {
        v = (threadIdx.x < 8) ? sh[threadIdx.x] : 0.f;
        #pragma unroll
        for (int o = 4; o; o >>= 1) v += __shfl_down_sync(0xffffffffu, v, o);
        if (lane == 0) sh[0] = v;
    }
    __syncthreads();
    return sh[0];
}

__device__ __forceinline__ float blockReduceMax(float v, volatile float* sh) {
    int lane = threadIdx.x & 31, w = threadIdx.x >> 5;
    #pragma unroll
    for (int o = 16; o; o >>= 1) v = fmaxf(v, __shfl_down_sync(0xffffffffu, v, o));
    if (lane == 0) sh[w] = v;
    __syncthreads();
    if (threadIdx.x < 32) {
        v = (threadIdx.x < 8) ? sh[threadIdx.x] : -3.0e38f;
        #pragma unroll
        for (int o = 4; o; o >>= 1) v = fmaxf(v, __shfl_down_sync(0xffffffffu, v, o));
        if (lane == 0) sh[0] = v;
    }
    __syncthreads();
    return sh[0];
}

// ---------------- layernorm --------------------------------------------------
__global__ void __launch_bounds__(256)
layernorm_kernel(const float* __restrict__ X, const float* __restrict__ g,
                 const float* __restrict__ b, float* __restrict__ Y)
{
    long long row = blockIdx.x;
    const float* x = X + row * DIM;
    __shared__ float sh0[8], sh1[8];
    float v0 = x[threadIdx.x], v1 = x[threadIdx.x + 256], v2 = x[threadIdx.x + 512];
    float sum  = blockReduceSum(v0 + v1 + v2, sh0);
    float sum2 = blockReduceSum(v0 * v0 + v1 * v1 + v2 * v2, sh1);
    float m   = sum * (1.f / DIM);
    float var = sum2 * (1.f / DIM) - m * m;
    float inv = rsqrtf(var + 1e-5f);
    float* y = Y + row * DIM;
    #pragma unroll
    for (int i = 0; i < 3; i++) {
        int c = threadIdx.x + i * 256;
        float xv = (i == 0) ? v0 : (i == 1) ? v1 : v2;
        y[c] = (xv - m) * inv * g[c] + b[c];
    }
}

// ---------------- single-pass softmax over padded rows (stride SEQP) ---------
// Reads once into registers, writes once; zeroes padded cols [SEQ, SEQP).
__global__ void __launch_bounds__(256)
softmax_kernel(float* __restrict__ S)
{
    long long row = blockIdx.x;
    float* p = S + row * SEQP;
    __shared__ float sh[8];
    int t = threadIdx.x;

    float x0 = (t       < SEQ) ? p[t      ] : -3.0e38f;
    float x1 = (t + 256 < SEQ) ? p[t + 256] : -3.0e38f;
    float x2 = (t + 512 < SEQ) ? p[t + 512] : -3.0e38f;

    float mx = blockReduceMax(fmaxf(x0, fmaxf(x1, x2)), sh);
    __syncthreads();

    float e0 = (t       < SEQ) ? __expf(x0 - mx) : 0.f;
    float e1 = (t + 256 < SEQ) ? __expf(x1 - mx) : 0.f;
    float e2 = (t + 512 < SEQ) ? __expf(x2 - mx) : 0.f;

    float s = blockReduceSum(e0 + e1 + e2, sh);
    float inv = 1.f / s;

    if (t       < SEQP) p[t      ] = (t       < SEQ) ? e0 * inv : 0.f;
    if (t + 256 < SEQP) p[t + 256] = (t + 256 < SEQ) ? e1 * inv : 0.f;
    if (t + 512 < SEQP) p[t + 512] = (t + 512 < SEQ) ? e2 * inv : 0.f;
}

// ---------------- patchify ----------------------------------------------------
__global__ void __launch_bounds__(256)
patchify_kernel(const float* __restrict__ img)
{
    int idx = blockIdx.x * 256 + threadIdx.x;
    if (idx >= BATCH * NPATCH * PDIM) return;
    int pd = idx % PDIM;
    int t  = idx / PDIM;
    int patch = t % NPATCH;
    int b     = t / NPATCH;
    int c  = pd % 3;
    int pp = pd / 3;
    int p2 = pp % PSZ, p1 = pp / PSZ;
    int wx = patch % HP, hy = patch / HP;
    g_P[idx] = img[(((long long)b * 3 + c) * IMGH + hy * PSZ + p1) * IMGH + wx * PSZ + p2];
}

// ---------------- assemble: cls + pos add ------------------------------------
__global__ void __launch_bounds__(256)
assemble_kernel(const float* __restrict__ emb, const float* __restrict__ cls,
                const float* __restrict__ pos)
{
    int idx = blockIdx.x * 256 + threadIdx.x;
    if (idx >= BATCH * SEQ * DIM) return;
    int d = idx % DIM;
    int t = idx / DIM;
    int s = t % SEQ;
    int b = t / SEQ;
    float v;
    if (s == 0) v = cls[d] + pos[d];
    else        v = emb[((long long)b * NPATCH + (s - 1)) * DIM + d] + pos[(long long)s * DIM + d];
    g_X[idx] = v;
}

// ---------------- output: drop cls token -------------------------------------
__global__ void __launch_bounds__(256)
output_kernel(float* __restrict__ out)
{
    int idx = blockIdx.x * 256 + threadIdx.x;
    if (idx >= BATCH * NPATCH * DIM) return;
    int d = idx % DIM;
    int t = idx / DIM;
    int s = t % NPATCH;
    int b = t / NPATCH;
    out[idx] = g_X[((long long)b * SEQ + (s + 1)) * DIM + d];
}

// ---------------- host driver ------------------------------------------------
extern "C" void kernel_launch(void* const* d_in, const int* in_sizes, int n_in,
                              void* d_out, int out_size)
{
    const float* img   = (const float*)d_in[0];
    const float* pos   = (const float*)d_in[1];
    const float* cls   = (const float*)d_in[2];
    const float* pw    = (const float*)d_in[3];
    const float* pb    = (const float*)d_in[4];
    const float* ln1g  = (const float*)d_in[5];
    const float* ln1b  = (const float*)d_in[6];
    const float* qkvw  = (const float*)d_in[7];
    const float* outw  = (const float*)d_in[8];
    const float* outb  = (const float*)d_in[9];
    const float* ln2g  = (const float*)d_in[10];
    const float* ln2b  = (const float*)d_in[11];
    const float* ff1w  = (const float*)d_in[12];
    const float* ff1b  = (const float*)d_in[13];
    const float* ff2w  = (const float*)d_in[14];
    const float* ff2b  = (const float*)d_in[15];
    float* out = (float*)d_out;

    float *pX, *pY, *pQKV, *pS, *pO, *pH, *pP;
    cudaGetSymbolAddress((void**)&pX,   g_X);
    cudaGetSymbolAddress((void**)&pY,   g_Y);
    cudaGetSymbolAddress((void**)&pQKV, g_QKV);
    cudaGetSymbolAddress((void**)&pS,   g_S);
    cudaGetSymbolAddress((void**)&pO,   g_O);
    cudaGetSymbolAddress((void**)&pH,   g_H);
    cudaGetSymbolAddress((void**)&pP,   g_P);

    const int Mfull = BATCH * SEQ;
    const int Mpat  = BATCH * NPATCH;

    // dynamic smem sizes per instantiation
    const int SM_NN  = (2 * 128 * 36 + 2 * 32 * 132) * 4;   // 70656
    const int SM_TT  = (2 * 128 * 36 + 2 * 128 * 36) * 4;   // 73728
    const int SM_PV  = (2 * 128 * 36 + 2 * 32 * 68) * 4;    // 54272

    static int attr_done = 0;
    if (!attr_done) {
        cudaFuncSetAttribute((const void*)gemm_tc<128,128,32,2,4,false>,
                             cudaFuncAttributeMaxDynamicSharedMemorySize, SM_NN);
        cudaFuncSetAttribute((const void*)gemm_tc<128,128,32,2,4,true>,
                             cudaFuncAttributeMaxDynamicSharedMemorySize, SM_TT);
        cudaFuncSetAttribute((const void*)gemm_tc<128,64,32,4,2,false>,
                             cudaFuncAttributeMaxDynamicSharedMemorySize, SM_PV);
        attr_done = 1;
    }

    auto grid = [](int M, int N, int BMv, int BNv, int Z) {
        return dim3((N + BNv - 1) / BNv, (M + BMv - 1) / BMv, Z);
    };

    // 1) patchify + patch embed + assemble
    patchify_kernel<<<(BATCH * NPATCH * PDIM + 255) / 256, 256>>>(img);
    gemm_tc<128,128,32,2,4,false><<<grid(Mpat, DIM, 128, 128, 1), 256, SM_NN>>>(
        pP, PDIM, 0, 0,  pw, DIM, 0, 0,  pb,
        pY, DIM, 0, 0,  Mpat, DIM, PDIM, 0);
    assemble_kernel<<<(BATCH * SEQ * DIM + 255) / 256, 256>>>(pY, cls, pos);

    // 2) transformer layers
    for (int l = 0; l < DEPTH; l++) {
        const float* wqkv = qkvw + (long long)l * DIM * 3 * DIM;
        const float* wo   = outw + (long long)l * DIM * DIM;
        const float* bo   = outb + (long long)l * DIM;
        const float* w1   = ff1w + (long long)l * DIM * MLPD;
        const float* b1   = ff1b + (long long)l * MLPD;
        const float* w2   = ff2w + (long long)l * MLPD * DIM;
        const float* b2   = ff2b + (long long)l * DIM;

        layernorm_kernel<<<Mfull, 256>>>(pX, ln1g + (long long)l * DIM,
                                         ln1b + (long long)l * DIM, pY);
        // QKV = Y @ Wqkv
        gemm_tc<128,128,32,2,4,false><<<grid(Mfull, 3 * DIM, 128, 128, 1), 256, SM_NN>>>(
            pY, DIM, 0, 0,  wqkv, 3 * DIM, 0, 0,  nullptr,
            pQKV, 3 * DIM, 0, 0,  Mfull, 3 * DIM, DIM, 0);
        // S = Q @ K^T per (b,h), C padded to SEQP
        gemm_tc<128,128,32,2,4,true><<<grid(SEQ, SEQ, 128, 128, BATCH * HEADS), 256, SM_TT>>>(
            pQKV,       3 * DIM, (long long)SEQ * 3 * DIM, HDIM,
            pQKV + DIM, 3 * DIM, (long long)SEQ * 3 * DIM, HDIM,
            nullptr,
            pS, SEQP, (long long)HEADS * SEQ * SEQP, (long long)SEQ * SEQP,
            SEQ, SEQ, HDIM, 0);
        softmax_kernel<<<BATCH * HEADS * SEQ, 256>>>(pS);
        // O = P @ V per (b,h); K runs over padded SEQP (zero scores x pad)
        gemm_tc<128,64,32,4,2,false><<<grid(SEQ, HDIM, 128, 64, BATCH * HEADS), 256, SM_PV>>>(
            pS, SEQP, (long long)HEADS * SEQ * SEQP, (long long)SEQ * SEQP,
            pQKV + 2 * DIM, 3 * DIM, (long long)SEQ * 3 * DIM, HDIM,
            nullptr,
            pO, DIM, (long long)SEQ * DIM, HDIM,
            SEQ, HDIM, SEQP, 0);
        // X += O @ Wo + bo
        gemm_tc<128,128,32,2,4,false><<<grid(Mfull, DIM, 128, 128, 1), 256, SM_NN>>>(
            pO, DIM, 0, 0,  wo, DIM, 0, 0,  bo,
            pX, DIM, 0, 0,  Mfull, DIM, DIM, 2);
        layernorm_kernel<<<Mfull, 256>>>(pX, ln2g + (long long)l * DIM,
                                         ln2b + (long long)l * DIM, pY);
        // H = gelu(Y @ W1 + b1)
        gemm_tc<128,128,32,2,4,false><<<grid(Mfull, MLPD, 128, 128, 1), 256, SM_NN>>>(
            pY, DIM, 0, 0,  w1, MLPD, 0, 0,  b1,
            pH, MLPD, 0, 0,  Mfull, MLPD, DIM, 1);
        // X += H @ W2 + b2
        gemm_tc<128,128,32,2,4,false><<<grid(Mfull, DIM, 128, 128, 1), 256, SM_NN>>>(
            pH, MLPD, 0, 0,  w2, DIM, 0, 0,  b2,
            pX, DIM, 0, 0,  Mfull, DIM, MLPD, 2);
    }

    // 3) drop cls token -> output
    output_kernel<<<(BATCH * NPATCH * DIM + 255) / 256, 256>>>(out);
}

// round 5
// speedup vs baseline: 1.2815x; 1.2815x over previous
#include <cuda_runtime.h>
#include <math.h>

#define BATCH  8
#define SEQ    577
#define SEQP   608          // padded score row stride (multiple of 32, 16B-aligned)
#define DIM    768
#define HEADS  12
#define HDIM   64
#define MLPD   3072
#define DEPTH  8
#define NPATCH 576
#define PDIM   768
#define IMGH   384
#define PSZ    16
#define HP     24

// ---------------- scratch (device globals; allocation is banned) ------------
__device__ float g_X  [BATCH * SEQ * DIM];
__device__ float g_Y  [BATCH * SEQ * DIM];
__device__ float g_QKV[BATCH * SEQ * 3 * DIM + 64 * 3 * DIM]; // tail pad: PV K=SEQP overrun (zero-init)
__device__ float g_S  [BATCH * HEADS * SEQ * SEQP];
__device__ float g_O  [BATCH * SEQ * DIM];
__device__ float g_H  [BATCH * SEQ * MLPD];
__device__ float g_P  [BATCH * NPATCH * PDIM];

// ---------------- tf32 helpers ----------------------------------------------
__device__ __forceinline__ unsigned f2tf(float f) {
    unsigned u;
    asm("cvt.rna.tf32.f32 %0, %1;" : "=r"(u) : "f"(f));
    return u;
}

#define MMA_TF32(d, a, b)                                                     \
    asm volatile("mma.sync.aligned.m16n8k8.row.col.f32.tf32.tf32.f32 "        \
                 "{%0,%1,%2,%3}, {%4,%5,%6,%7}, {%8,%9}, {%0,%1,%2,%3};\n"    \
                 : "+f"(d[0]), "+f"(d[1]), "+f"(d[2]), "+f"(d[3])             \
                 : "r"(a[0]), "r"(a[1]), "r"(a[2]), "r"(a[3]),                \
                   "r"(b[0]), "r"(b[1]))

// ---------------- generic batched tf32 tensor-core GEMM ----------------------
// C[z] = op( A[z] @ B[z] (+ bias) ), fuse: 0=none, 1=gelu(exact), 2=residual
// Register-staged software pipeline (round-3 proven core): global loads for
// tile t+1 staged in registers during the MMA loop of tile t; tf32 conversion
// happens once at smem-store time (off the LDS->MMA critical path).
template<int BM, int BN, int BK, int WM, int WN>
__global__ void __launch_bounds__(WM * WN * 32)
gemm_tc(const float* __restrict__ A, int lda, long long sAb, long long sAh, int vecA,
        const float* __restrict__ Bm, int ldb, long long sBb, long long sBh, int transB,
        const float* __restrict__ bias,
        float* __restrict__ C, int ldc, long long sCb, long long sCh,
        int M, int N, int K, int fuse)
{
    constexpr int NTHREADS = WM * WN * 32;
    constexpr int MT = (BM / WM) / 16;
    constexpr int NT = (BN / WN) / 8;
    constexpr int A_IT = BM * BK / (NTHREADS * 4);
    constexpr int B_IT = BK * BN / (NTHREADS * 4);
    constexpr int APAD = 4;               // row stride 36 -> conflict-free fragments
    constexpr int BPAD = 4;

    __shared__ unsigned As[BM][BK + APAD];   // [m][k]
    __shared__ unsigned Bs[BK][BN + BPAD];   // [k][n]

    int z  = blockIdx.z;
    int zb = z / HEADS, zh = z % HEADS;
    A  += zb * sAb + zh * sAh;
    Bm += zb * sBb + zh * sBh;
    C  += zb * sCb + zh * sCh;

    int r0 = blockIdx.y * BM;
    int c0 = blockIdx.x * BN;
    int tid  = threadIdx.x;
    int wid  = tid >> 5, lane = tid & 31;
    int wm   = wid / WN, wn = wid % WN;
    int q    = lane >> 2, r = lane & 3;

    float acc[MT][NT][4];
    #pragma unroll
    for (int i = 0; i < MT; i++)
        #pragma unroll
        for (int j = 0; j < NT; j++)
            #pragma unroll
            for (int t = 0; t < 4; t++) acc[i][j][t] = 0.f;

    float4 rA[A_IT], rB[B_IT];

    auto gloadA = [&](int k0) {
        #pragma unroll
        for (int it = 0; it < A_IT; it++) {
            int idx = (tid + it * NTHREADS) * 4;
            int m = idx / BK, kk = idx % BK;
            float4 v = make_float4(0.f, 0.f, 0.f, 0.f);
            if (r0 + m < M) {
                const float* p = A + (long long)(r0 + m) * lda + k0 + kk;
                if (vecA && k0 + kk + 3 < K) {
                    v = *(const float4*)p;
                } else {
                    if (k0 + kk     < K) v.x = p[0];
                    if (k0 + kk + 1 < K) v.y = p[1];
                    if (k0 + kk + 2 < K) v.z = p[2];
                    if (k0 + kk + 3 < K) v.w = p[3];
                }
            }
            rA[it] = v;
        }
    };
    auto gloadB = [&](int k0) {
        if (!transB) {
            #pragma unroll
            for (int it = 0; it < B_IT; it++) {
                int idx = (tid + it * NTHREADS) * 4;
                int kk = idx / BN, n = idx % BN;
                float4 v = make_float4(0.f, 0.f, 0.f, 0.f);
                if (k0 + kk < K) {
                    const float* p = Bm + (long long)(k0 + kk) * ldb + c0 + n;
                    if (c0 + n + 3 < N) {
                        v = *(const float4*)p;
                    } else {
                        if (c0 + n     < N) v.x = p[0];
                        if (c0 + n + 1 < N) v.y = p[1];
                        if (c0 + n + 2 < N) v.z = p[2];
                        if (c0 + n + 3 < N) v.w = p[3];
                    }
                }
                rB[it] = v;
            }
        } else {
            #pragma unroll
            for (int it = 0; it < B_IT; it++) {
                int idx = (tid + it * NTHREADS) * 4;
                int n = idx / BK, kk = idx % BK;
                float4 v = make_float4(0.f, 0.f, 0.f, 0.f);
                if (c0 + n < N) {
                    const float* p = Bm + (long long)(c0 + n) * ldb + k0 + kk;
                    if (k0 + kk + 3 < K) {
                        v = *(const float4*)p;
                    } else {
                        if (k0 + kk     < K) v.x = p[0];
                        if (k0 + kk + 1 < K) v.y = p[1];
                        if (k0 + kk + 2 < K) v.z = p[2];
                        if (k0 + kk + 3 < K) v.w = p[3];
                    }
                }
                rB[it] = v;
            }
        }
    };
    auto sstore = [&]() {
        #pragma unroll
        for (int it = 0; it < A_IT; it++) {
            int idx = (tid + it * NTHREADS) * 4;
            int m = idx / BK, kk = idx % BK;
            As[m][kk + 0] = f2tf(rA[it].x);
            As[m][kk + 1] = f2tf(rA[it].y);
            As[m][kk + 2] = f2tf(rA[it].z);
            As[m][kk + 3] = f2tf(rA[it].w);
        }
        if (!transB) {
            #pragma unroll
            for (int it = 0; it < B_IT; it++) {
                int idx = (tid + it * NTHREADS) * 4;
                int kk = idx / BN, n = idx % BN;
                Bs[kk][n + 0] = f2tf(rB[it].x);
                Bs[kk][n + 1] = f2tf(rB[it].y);
                Bs[kk][n + 2] = f2tf(rB[it].z);
                Bs[kk][n + 3] = f2tf(rB[it].w);
            }
        } else {
            #pragma unroll
            for (int it = 0; it < B_IT; it++) {
                int idx = (tid + it * NTHREADS) * 4;
                int n = idx / BK, kk = idx % BK;
                Bs[kk + 0][n] = f2tf(rB[it].x);
                Bs[kk + 1][n] = f2tf(rB[it].y);
                Bs[kk + 2][n] = f2tf(rB[it].z);
                Bs[kk + 3][n] = f2tf(rB[it].w);
            }
        }
    };

    int T = (K + BK - 1) / BK;
    gloadA(0); gloadB(0);

    for (int t = 0; t < T; t++) {
        sstore();
        __syncthreads();
        if (t + 1 < T) {
            gloadA((t + 1) * BK);
            gloadB((t + 1) * BK);
        }
        #pragma unroll
        for (int kk = 0; kk < BK; kk += 8) {
            unsigned af[MT][4];
            unsigned bf[NT][2];
            #pragma unroll
            for (int i = 0; i < MT; i++) {
                int m = wm * (BM / WM) + i * 16;
                af[i][0] = As[m + q    ][kk + r    ];
                af[i][1] = As[m + q + 8][kk + r    ];
                af[i][2] = As[m + q    ][kk + r + 4];
                af[i][3] = As[m + q + 8][kk + r + 4];
            }
            #pragma unroll
            for (int j = 0; j < NT; j++) {
                int n = wn * (BN / WN) + j * 8;
                bf[j][0] = Bs[kk + r    ][n + q];
                bf[j][1] = Bs[kk + r + 4][n + q];
            }
            #pragma unroll
            for (int i = 0; i < MT; i++)
                #pragma unroll
                for (int j = 0; j < NT; j++)
                    MMA_TF32(acc[i][j], af[i], bf[j]);
        }
        __syncthreads();
    }

    // ---- epilogue ----
    #pragma unroll
    for (int i = 0; i < MT; i++) {
        #pragma unroll
        for (int j = 0; j < NT; j++) {
            #pragma unroll
            for (int t = 0; t < 4; t++) {
                int row = r0 + wm * (BM / WM) + i * 16 + q + ((t >= 2) ? 8 : 0);
                int col = c0 + wn * (BN / WN) + j * 8 + r * 2 + (t & 1);
                if (row >= M || col >= N) continue;
                float v = acc[i][j][t];
                if (bias) v += bias[col];
                if (fuse == 1) v = 0.5f * v * (1.f + erff(v * 0.70710678118654752f));
                long long off = (long long)row * ldc + col;
                if (fuse == 2) v += C[off];
                C[off] = v;
            }
        }
    }
}

// ---------------- reductions -------------------------------------------------
__device__ __forceinline__ float blockReduceSum(float v, volatile float* sh) {
    int lane = threadIdx.x & 31, w = threadIdx.x >> 5;
    #pragma unroll
    for (int o = 16; o; o >>= 1) v += __shfl_down_sync(0xffffffffu, v, o);
    if (lane == 0) sh[w] = v;
    __syncthreads();
    if (threadIdx.x < 32) {
        v = (threadIdx.x < 8) ? sh[threadIdx.x] : 0.f;
        #pragma unroll
        for (int o = 4; o; o >>= 1) v += __shfl_down_sync(0xffffffffu, v, o);
        if (lane == 0) sh[0] = v;
    }
    __syncthreads();
    return sh[0];
}

__device__ __forceinline__ float blockReduceMax(float v, volatile float* sh) {
    int lane = threadIdx.x & 31, w = threadIdx.x >> 5;
    #pragma unroll
    for (int o = 16; o; o >>= 1) v = fmaxf(v, __shfl_down_sync(0xffffffffu, v, o));
    if (lane == 0) sh[w] = v;
    __syncthreads();
    if (threadIdx.x < 32) {
        v = (threadIdx.x < 8) ? sh[threadIdx.x] : -3.0e38f;
        #pragma unroll
        for (int o = 4; o; o >>= 1) v = fmaxf(v, __shfl_down_sync(0xffffffffu, v, o));
        if (lane == 0) sh[0] = v;
    }
    __syncthreads();
    return sh[0];
}

// ---------------- layernorm --------------------------------------------------
__global__ void __launch_bounds__(256)
layernorm_kernel(const float* __restrict__ X, const float* __restrict__ g,
                 const float* __restrict__ b, float* __restrict__ Y)
{
    long long row = blockIdx.x;
    const float* x = X + row * DIM;
    __shared__ float sh0[8], sh1[8];
    float v0 = x[threadIdx.x], v1 = x[threadIdx.x + 256], v2 = x[threadIdx.x + 512];
    float sum  = blockReduceSum(v0 + v1 + v2, sh0);
    float sum2 = blockReduceSum(v0 * v0 + v1 * v1 + v2 * v2, sh1);
    float m   = sum * (1.f / DIM);
    float var = sum2 * (1.f / DIM) - m * m;
    float inv = rsqrtf(var + 1e-5f);
    float* y = Y + row * DIM;
    #pragma unroll
    for (int i = 0; i < 3; i++) {
        int c = threadIdx.x + i * 256;
        float xv = (i == 0) ? v0 : (i == 1) ? v1 : v2;
        y[c] = (xv - m) * inv * g[c] + b[c];
    }
}

// ---------------- single-pass softmax over padded rows (stride SEQP) ---------
__global__ void __launch_bounds__(256)
softmax_kernel(float* __restrict__ S)
{
    long long row = blockIdx.x;
    float* p = S + row * SEQP;
    __shared__ float sh[8];
    int t = threadIdx.x;

    float x0 = (t       < SEQ) ? p[t      ] : -3.0e38f;
    float x1 = (t + 256 < SEQ) ? p[t + 256] : -3.0e38f;
    float x2 = (t + 512 < SEQ) ? p[t + 512] : -3.0e38f;

    float mx = blockReduceMax(fmaxf(x0, fmaxf(x1, x2)), sh);
    __syncthreads();

    float e0 = (t       < SEQ) ? __expf(x0 - mx) : 0.f;
    float e1 = (t + 256 < SEQ) ? __expf(x1 - mx) : 0.f;
    float e2 = (t + 512 < SEQ) ? __expf(x2 - mx) : 0.f;

    float s = blockReduceSum(e0 + e1 + e2, sh);
    float inv = 1.f / s;

    if (t       < SEQP) p[t      ] = (t       < SEQ) ? e0 * inv : 0.f;
    if (t + 256 < SEQP) p[t + 256] = (t + 256 < SEQ) ? e1 * inv : 0.f;
    if (t + 512 < SEQP) p[t + 512] = (t + 512 < SEQ) ? e2 * inv : 0.f;
}

// ---------------- patchify ----------------------------------------------------
__global__ void __launch_bounds__(256)
patchify_kernel(const float* __restrict__ img)
{
    int idx = blockIdx.x * 256 + threadIdx.x;
    if (idx >= BATCH * NPATCH * PDIM) return;
    int pd = idx % PDIM;
    int t  = idx / PDIM;
    int patch = t % NPATCH;
    int b     = t / NPATCH;
    int c  = pd % 3;
    int pp = pd / 3;
    int p2 = pp % PSZ, p1 = pp / PSZ;
    int wx = patch % HP, hy = patch / HP;
    g_P[idx] = img[(((long long)b * 3 + c) * IMGH + hy * PSZ + p1) * IMGH + wx * PSZ + p2];
}

// ---------------- assemble: cls + pos add ------------------------------------
__global__ void __launch_bounds__(256)
assemble_kernel(const float* __restrict__ emb, const float* __restrict__ cls,
                const float* __restrict__ pos)
{
    int idx = blockIdx.x * 256 + threadIdx.x;
    if (idx >= BATCH * SEQ * DIM) return;
    int d = idx % DIM;
    int t = idx / DIM;
    int s = t % SEQ;
    int b = t / SEQ;
    float v;
    if (s == 0) v = cls[d] + pos[d];
    else        v = emb[((long long)b * NPATCH + (s - 1)) * DIM + d] + pos[(long long)s * DIM + d];
    g_X[idx] = v;
}

// ---------------- output: drop cls token -------------------------------------
__global__ void __launch_bounds__(256)
output_kernel(float* __restrict__ out)
{
    int idx = blockIdx.x * 256 + threadIdx.x;
    if (idx >= BATCH * NPATCH * DIM) return;
    int d = idx % DIM;
    int t = idx / DIM;
    int s = t % NPATCH;
    int b = t / NPATCH;
    out[idx] = g_X[((long long)b * SEQ + (s + 1)) * DIM + d];
}

// ---------------- host driver ------------------------------------------------
extern "C" void kernel_launch(void* const* d_in, const int* in_sizes, int n_in,
                              void* d_out, int out_size)
{
    const float* img   = (const float*)d_in[0];
    const float* pos   = (const float*)d_in[1];
    const float* cls   = (const float*)d_in[2];
    const float* pw    = (const float*)d_in[3];
    const float* pb    = (const float*)d_in[4];
    const float* ln1g  = (const float*)d_in[5];
    const float* ln1b  = (const float*)d_in[6];
    const float* qkvw  = (const float*)d_in[7];
    const float* outw  = (const float*)d_in[8];
    const float* outb  = (const float*)d_in[9];
    const float* ln2g  = (const float*)d_in[10];
    const float* ln2b  = (const float*)d_in[11];
    const float* ff1w  = (const float*)d_in[12];
    const float* ff1b  = (const float*)d_in[13];
    const float* ff2w  = (const float*)d_in[14];
    const float* ff2b  = (const float*)d_in[15];
    float* out = (float*)d_out;

    float *pX, *pY, *pQKV, *pS, *pO, *pH, *pP;
    cudaGetSymbolAddress((void**)&pX,   g_X);
    cudaGetSymbolAddress((void**)&pY,   g_Y);
    cudaGetSymbolAddress((void**)&pQKV, g_QKV);
    cudaGetSymbolAddress((void**)&pS,   g_S);
    cudaGetSymbolAddress((void**)&pO,   g_O);
    cudaGetSymbolAddress((void**)&pH,   g_H);
    cudaGetSymbolAddress((void**)&pP,   g_P);

    const int Mfull = BATCH * SEQ;
    const int Mpat  = BATCH * NPATCH;

    auto grid = [](int M, int N, int BMv, int BNv, int Z) {
        return dim3((N + BNv - 1) / BNv, (M + BMv - 1) / BMv, Z);
    };

    // 1) patchify + patch embed + assemble
    patchify_kernel<<<(BATCH * NPATCH * PDIM + 255) / 256, 256>>>(img);
    gemm_tc<128,128,32,2,4><<<grid(Mpat, DIM, 128, 128, 1), 256>>>(
        pP, PDIM, 0, 0, 1,  pw, DIM, 0, 0, 0,  pb,
        pY, DIM, 0, 0,  Mpat, DIM, PDIM, 0);
    assemble_kernel<<<(BATCH * SEQ * DIM + 255) / 256, 256>>>(pY, cls, pos);

    // 2) transformer layers
    for (int l = 0; l < DEPTH; l++) {
        const float* wqkv = qkvw + (long long)l * DIM * 3 * DIM;
        const float* wo   = outw + (long long)l * DIM * DIM;
        const float* bo   = outb + (long long)l * DIM;
        const float* w1   = ff1w + (long long)l * DIM * MLPD;
        const float* b1   = ff1b + (long long)l * MLPD;
        const float* w2   = ff2w + (long long)l * MLPD * DIM;
        const float* b2   = ff2b + (long long)l * DIM;

        layernorm_kernel<<<Mfull, 256>>>(pX, ln1g + (long long)l * DIM,
                                         ln1b + (long long)l * DIM, pY);
        // QKV = Y @ Wqkv
        gemm_tc<128,128,32,2,4><<<grid(Mfull, 3 * DIM, 128, 128, 1), 256>>>(
            pY, DIM, 0, 0, 1,  wqkv, 3 * DIM, 0, 0, 0,  nullptr,
            pQKV, 3 * DIM, 0, 0,  Mfull, 3 * DIM, DIM, 0);
        // S = Q @ K^T per (b,h), written with padded row stride SEQP
        gemm_tc<128,128,32,2,4><<<grid(SEQ, SEQ, 128, 128, BATCH * HEADS), 256>>>(
            pQKV,       3 * DIM, (long long)SEQ * 3 * DIM, HDIM, 1,
            pQKV + DIM, 3 * DIM, (long long)SEQ * 3 * DIM, HDIM, 1,
            nullptr,
            pS, SEQP, (long long)HEADS * SEQ * SEQP, (long long)SEQ * SEQP,
            SEQ, SEQ, HDIM, 0);
        softmax_kernel<<<BATCH * HEADS * SEQ, 256>>>(pS);
        // O = P @ V per (b,h); A fully vectorized (lda=SEQP), K=SEQP (pad scores are 0)
        gemm_tc<128,64,32,4,2><<<grid(SEQ, HDIM, 128, 64, BATCH * HEADS), 256>>>(
            pS, SEQP, (long long)HEADS * SEQ * SEQP, (long long)SEQ * SEQP, 1,
            pQKV + 2 * DIM, 3 * DIM, (long long)SEQ * 3 * DIM, HDIM, 0,
            nullptr,
            pO, DIM, (long long)SEQ * DIM, HDIM,
            SEQ, HDIM, SEQP, 0);
        // X += O @ Wo + bo
        gemm_tc<128,128,32,2,4><<<grid(Mfull, DIM, 128, 128, 1), 256>>>(
            pO, DIM, 0, 0, 1,  wo, DIM, 0, 0, 0,  bo,
            pX, DIM, 0, 0,  Mfull, DIM, DIM, 2);
        layernorm_kernel<<<Mfull, 256>>>(pX, ln2g + (long long)l * DIM,
                                         ln2b + (long long)l * DIM, pY);
        // H = gelu(Y @ W1 + b1)
        gemm_tc<128,128,32,2,4><<<grid(Mfull, MLPD, 128, 128, 1), 256>>>(
            pY, DIM, 0, 0, 1,  w1, MLPD, 0, 0, 0,  b1,
            pH, MLPD, 0, 0,  Mfull, MLPD, DIM, 1);
        // X += H @ W2 + b2
        gemm_tc<128,128,32,2,4><<<grid(Mfull, DIM, 128, 128, 1), 256>>>(
            pH, MLPD, 0, 0, 1,  w2, DIM, 0, 0, 0,  b2,
            pX, DIM, 0, 0,  Mfull, DIM, MLPD, 2);
    }

    // 3) drop cls token -> output
    output_kernel<<<(BATCH * NPATCH * DIM + 255) / 256, 256>>>(out);
}

// round 8
// speedup vs baseline: 1.4344x; 1.1193x over previous
#include <cuda_runtime.h>
#include <math.h>

#define BATCH  8
#define SEQ    577
#define DIM    768
#define HEADS  12
#define HDIM   64
#define MLPD   3072
#define DEPTH  8
#define NPATCH 576
#define PDIM   768
#define IMGH   384
#define PSZ    16
#define HP     24

// ---------------- scratch (device globals; allocation is banned) ------------
__device__ float g_X  [BATCH * SEQ * DIM];
__device__ float g_Y  [BATCH * SEQ * DIM];
__device__ float g_QKV[BATCH * SEQ * 3 * DIM];
__device__ float g_O  [BATCH * SEQ * DIM];
__device__ float g_H  [BATCH * SEQ * MLPD];
__device__ float g_P  [BATCH * NPATCH * PDIM];

// ---------------- tf32 helpers ----------------------------------------------
__device__ __forceinline__ unsigned f2tf(float f) {
    unsigned u;
    asm("cvt.rna.tf32.f32 %0, %1;" : "=r"(u) : "f"(f));
    return u;
}

#define MMA_TF32(d, a, b)                                                     \
    asm volatile("mma.sync.aligned.m16n8k8.row.col.f32.tf32.tf32.f32 "        \
                 "{%0,%1,%2,%3}, {%4,%5,%6,%7}, {%8,%9}, {%0,%1,%2,%3};\n"    \
                 : "+f"(d[0]), "+f"(d[1]), "+f"(d[2]), "+f"(d[3])             \
                 : "r"(a[0]), "r"(a[1]), "r"(a[2]), "r"(a[3]),                \
                   "r"(b[0]), "r"(b[1]))

// ---------------- generic batched tf32 tensor-core GEMM (round-3/5 core) -----
template<int BM, int BN, int BK, int WM, int WN>
__global__ void __launch_bounds__(WM * WN * 32)
gemm_tc(const float* __restrict__ A, int lda, long long sAb, long long sAh, int vecA,
        const float* __restrict__ Bm, int ldb, long long sBb, long long sBh, int transB,
        const float* __restrict__ bias,
        float* __restrict__ C, int ldc, long long sCb, long long sCh,
        int M, int N, int K, int fuse)
{
    constexpr int NTHREADS = WM * WN * 32;
    constexpr int MT = (BM / WM) / 16;
    constexpr int NT = (BN / WN) / 8;
    constexpr int A_IT = BM * BK / (NTHREADS * 4);
    constexpr int B_IT = BK * BN / (NTHREADS * 4);
    constexpr int APAD = 4;
    constexpr int BPAD = 4;

    __shared__ unsigned As[BM][BK + APAD];
    __shared__ unsigned Bs[BK][BN + BPAD];

    int z  = blockIdx.z;
    int zb = z / HEADS, zh = z % HEADS;
    A  += zb * sAb + zh * sAh;
    Bm += zb * sBb + zh * sBh;
    C  += zb * sCb + zh * sCh;

    int r0 = blockIdx.y * BM;
    int c0 = blockIdx.x * BN;
    int tid  = threadIdx.x;
    int wid  = tid >> 5, lane = tid & 31;
    int wm   = wid / WN, wn = wid % WN;
    int q    = lane >> 2, r = lane & 3;

    float acc[MT][NT][4];
    #pragma unroll
    for (int i = 0; i < MT; i++)
        #pragma unroll
        for (int j = 0; j < NT; j++)
            #pragma unroll
            for (int t = 0; t < 4; t++) acc[i][j][t] = 0.f;

    float4 rA[A_IT], rB[B_IT];

    auto gloadA = [&](int k0) {
        #pragma unroll
        for (int it = 0; it < A_IT; it++) {
            int idx = (tid + it * NTHREADS) * 4;
            int m = idx / BK, kk = idx % BK;
            float4 v = make_float4(0.f, 0.f, 0.f, 0.f);
            if (r0 + m < M) {
                const float* p = A + (long long)(r0 + m) * lda + k0 + kk;
                if (vecA && k0 + kk + 3 < K) {
                    v = *(const float4*)p;
                } else {
                    if (k0 + kk     < K) v.x = p[0];
                    if (k0 + kk + 1 < K) v.y = p[1];
                    if (k0 + kk + 2 < K) v.z = p[2];
                    if (k0 + kk + 3 < K) v.w = p[3];
                }
            }
            rA[it] = v;
        }
    };
    auto gloadB = [&](int k0) {
        if (!transB) {
            #pragma unroll
            for (int it = 0; it < B_IT; it++) {
                int idx = (tid + it * NTHREADS) * 4;
                int kk = idx / BN, n = idx % BN;
                float4 v = make_float4(0.f, 0.f, 0.f, 0.f);
                if (k0 + kk < K) {
                    const float* p = Bm + (long long)(k0 + kk) * ldb + c0 + n;
                    if (c0 + n + 3 < N) {
                        v = *(const float4*)p;
                    } else {
                        if (c0 + n     < N) v.x = p[0];
                        if (c0 + n + 1 < N) v.y = p[1];
                        if (c0 + n + 2 < N) v.z = p[2];
                        if (c0 + n + 3 < N) v.w = p[3];
                    }
                }
                rB[it] = v;
            }
        } else {
            #pragma unroll
            for (int it = 0; it < B_IT; it++) {
                int idx = (tid + it * NTHREADS) * 4;
                int n = idx / BK, kk = idx % BK;
                float4 v = make_float4(0.f, 0.f, 0.f, 0.f);
                if (c0 + n < N) {
                    const float* p = Bm + (long long)(c0 + n) * ldb + k0 + kk;
                    if (k0 + kk + 3 < K) {
                        v = *(const float4*)p;
                    } else {
                        if (k0 + kk     < K) v.x = p[0];
                        if (k0 + kk + 1 < K) v.y = p[1];
                        if (k0 + kk + 2 < K) v.z = p[2];
                        if (k0 + kk + 3 < K) v.w = p[3];
                    }
                }
                rB[it] = v;
            }
        }
    };
    auto sstore = [&]() {
        #pragma unroll
        for (int it = 0; it < A_IT; it++) {
            int idx = (tid + it * NTHREADS) * 4;
            int m = idx / BK, kk = idx % BK;
            As[m][kk + 0] = f2tf(rA[it].x);
            As[m][kk + 1] = f2tf(rA[it].y);
            As[m][kk + 2] = f2tf(rA[it].z);
            As[m][kk + 3] = f2tf(rA[it].w);
        }
        if (!transB) {
            #pragma unroll
            for (int it = 0; it < B_IT; it++) {
                int idx = (tid + it * NTHREADS) * 4;
                int kk = idx / BN, n = idx % BN;
                Bs[kk][n + 0] = f2tf(rB[it].x);
                Bs[kk][n + 1] = f2tf(rB[it].y);
                Bs[kk][n + 2] = f2tf(rB[it].z);
                Bs[kk][n + 3] = f2tf(rB[it].w);
            }
        } else {
            #pragma unroll
            for (int it = 0; it < B_IT; it++) {
                int idx = (tid + it * NTHREADS) * 4;
                int n = idx / BK, kk = idx % BK;
                Bs[kk + 0][n] = f2tf(rB[it].x);
                Bs[kk + 1][n] = f2tf(rB[it].y);
                Bs[kk + 2][n] = f2tf(rB[it].z);
                Bs[kk + 3][n] = f2tf(rB[it].w);
            }
        }
    };

    int T = (K + BK - 1) / BK;
    gloadA(0); gloadB(0);

    for (int t = 0; t < T; t++) {
        sstore();
        __syncthreads();
        if (t + 1 < T) {
            gloadA((t + 1) * BK);
            gloadB((t + 1) * BK);
        }
        #pragma unroll
        for (int kk = 0; kk < BK; kk += 8) {
            unsigned af[MT][4];
            unsigned bf[NT][2];
            #pragma unroll
            for (int i = 0; i < MT; i++) {
                int m = wm * (BM / WM) + i * 16;
                af[i][0] = As[m + q    ][kk + r    ];
                af[i][1] = As[m + q + 8][kk + r    ];
                af[i][2] = As[m + q    ][kk + r + 4];
                af[i][3] = As[m + q + 8][kk + r + 4];
            }
            #pragma unroll
            for (int j = 0; j < NT; j++) {
                int n = wn * (BN / WN) + j * 8;
                bf[j][0] = Bs[kk + r    ][n + q];
                bf[j][1] = Bs[kk + r + 4][n + q];
            }
            #pragma unroll
            for (int i = 0; i < MT; i++)
                #pragma unroll
                for (int j = 0; j < NT; j++)
                    MMA_TF32(acc[i][j], af[i], bf[j]);
        }
        __syncthreads();
    }

    #pragma unroll
    for (int i = 0; i < MT; i++) {
        #pragma unroll
        for (int j = 0; j < NT; j++) {
            #pragma unroll
            for (int t = 0; t < 4; t++) {
                int row = r0 + wm * (BM / WM) + i * 16 + q + ((t >= 2) ? 8 : 0);
                int col = c0 + wn * (BN / WN) + j * 8 + r * 2 + (t & 1);
                if (row >= M || col >= N) continue;
                float v = acc[i][j][t];
                if (bias) v += bias[col];
                if (fuse == 1) v = 0.5f * v * (1.f + erff(v * 0.70710678118654752f));
                long long off = (long long)row * ldc + col;
                if (fuse == 2) v += C[off];
                C[off] = v;
            }
        }
    }
}

// ---------------- fused flash attention --------------------------------------
// One CTA per (b, h, 128-query tile). Q tile smem-resident; loop over 64-key
// chunks: S = Q@K^T (tf32 mma), online softmax in registers, P routed through
// smem (fragment layout) into PV mma. Scores never touch HBM.
// sK and sV are BOTH stored [key][d] (natural). For the PV B-fragment,
// bb[0] = sV[(kk+r)*QSTR + n] = V[key=kk+r][d=n] == B[k][n] as mma requires.
#define BQ   128
#define BKC  64
#define QSTR 68       // padded word stride -> conflict-free fragment LDS

__global__ void __launch_bounds__(256)
flash_attn_kernel(const float* __restrict__ QKV, float* __restrict__ O)
{
    extern __shared__ unsigned fa_sm[];
    unsigned* sQ = fa_sm;                   // [BQ ][QSTR]
    unsigned* sK = sQ + BQ  * QSTR;         // [BKC][QSTR]  [key][d]
    unsigned* sV = sK + BKC * QSTR;         // [BKC][QSTR]  [key][d]
    unsigned* sP = sV + BKC * QSTR;         // [BQ ][QSTR]

    int z  = blockIdx.z;
    int b  = z / HEADS, h = z % HEADS;
    int q0 = blockIdx.y * BQ;

    const float* Qg = QKV + (long long)b * SEQ * (3 * DIM) + h * HDIM;
    const float* Kg = Qg + DIM;
    const float* Vg = Qg + 2 * DIM;

    int tid  = threadIdx.x;
    int wid  = tid >> 5, lane = tid & 31;
    int qr   = lane >> 2, r = lane & 3;
    int mrow = wid * 16;                     // warp's 16-row band

    // ---- load Q tile (once) ----
    #pragma unroll
    for (int it = 0; it < BQ * HDIM / (256 * 4); it++) {
        int idx = (tid + it * 256) * 4;
        int m = idx / HDIM, d = idx % HDIM;
        float4 v = make_float4(0.f, 0.f, 0.f, 0.f);
        if (q0 + m < SEQ)
            v = *(const float4*)(Qg + (long long)(q0 + m) * (3 * DIM) + d);
        sQ[m * QSTR + d + 0] = f2tf(v.x);
        sQ[m * QSTR + d + 1] = f2tf(v.y);
        sQ[m * QSTR + d + 2] = f2tf(v.z);
        sQ[m * QSTR + d + 3] = f2tf(v.w);
    }

    float acc_O[8][4];
    #pragma unroll
    for (int j = 0; j < 8; j++)
        #pragma unroll
        for (int t = 0; t < 4; t++) acc_O[j][t] = 0.f;
    float mstate[2] = { -3.0e38f, -3.0e38f };
    float lstate[2] = { 0.f, 0.f };

    const int nchunks = (SEQ + BKC - 1) / BKC;
    for (int c = 0; c < nchunks; c++) {
        int kb = c * BKC;
        __syncthreads();   // protect sK/sV reuse (also covers first-iter sQ)

        // ---- load K chunk [key][d] ----
        #pragma unroll
        for (int it = 0; it < BKC * HDIM / (256 * 4); it++) {
            int idx = (tid + it * 256) * 4;
            int n = idx / HDIM, d = idx % HDIM;
            float4 v = make_float4(0.f, 0.f, 0.f, 0.f);
            if (kb + n < SEQ)
                v = *(const float4*)(Kg + (long long)(kb + n) * (3 * DIM) + d);
            sK[n * QSTR + d + 0] = f2tf(v.x);
            sK[n * QSTR + d + 1] = f2tf(v.y);
            sK[n * QSTR + d + 2] = f2tf(v.z);
            sK[n * QSTR + d + 3] = f2tf(v.w);
        }
        // ---- load V chunk [key][d] (natural layout) ----
        #pragma unroll
        for (int it = 0; it < BKC * HDIM / (256 * 4); it++) {
            int idx = (tid + it * 256) * 4;
            int n = idx / HDIM, d = idx % HDIM;
            float4 v = make_float4(0.f, 0.f, 0.f, 0.f);
            if (kb + n < SEQ)
                v = *(const float4*)(Vg + (long long)(kb + n) * (3 * DIM) + d);
            sV[n * QSTR + d + 0] = f2tf(v.x);
            sV[n * QSTR + d + 1] = f2tf(v.y);
            sV[n * QSTR + d + 2] = f2tf(v.z);
            sV[n * QSTR + d + 3] = f2tf(v.w);
        }
        __syncthreads();

        // ---- S = Q @ K^T for this chunk ----
        float acc_S[8][4];
        #pragma unroll
        for (int j = 0; j < 8; j++)
            #pragma unroll
            for (int t = 0; t < 4; t++) acc_S[j][t] = 0.f;

        #pragma unroll
        for (int kk = 0; kk < HDIM; kk += 8) {
            unsigned a[4] = { sQ[(mrow + qr    ) * QSTR + kk + r    ],
                              sQ[(mrow + qr + 8) * QSTR + kk + r    ],
                              sQ[(mrow + qr    ) * QSTR + kk + r + 4],
                              sQ[(mrow + qr + 8) * QSTR + kk + r + 4] };
            #pragma unroll
            for (int j = 0; j < 8; j++) {
                unsigned bb[2] = { sK[(j * 8 + qr) * QSTR + kk + r    ],
                                   sK[(j * 8 + qr) * QSTR + kk + r + 4] };
                MMA_TF32(acc_S[j], a, bb);
            }
        }

        // ---- mask invalid keys, online softmax ----
        float cmax[2] = { -3.0e38f, -3.0e38f };
        #pragma unroll
        for (int j = 0; j < 8; j++)
            #pragma unroll
            for (int t = 0; t < 4; t++) {
                int col = j * 8 + r * 2 + (t & 1);
                if (kb + col >= SEQ) acc_S[j][t] = -3.0e38f;
                cmax[t >> 1] = fmaxf(cmax[t >> 1], acc_S[j][t]);
            }
        #pragma unroll
        for (int o = 1; o <= 2; o <<= 1) {
            cmax[0] = fmaxf(cmax[0], __shfl_xor_sync(0xffffffffu, cmax[0], o));
            cmax[1] = fmaxf(cmax[1], __shfl_xor_sync(0xffffffffu, cmax[1], o));
        }
        float mnew[2]  = { fmaxf(mstate[0], cmax[0]), fmaxf(mstate[1], cmax[1]) };
        float scale[2] = { __expf(mstate[0] - mnew[0]), __expf(mstate[1] - mnew[1]) };
        float csum[2] = { 0.f, 0.f };
        #pragma unroll
        for (int j = 0; j < 8; j++)
            #pragma unroll
            for (int t = 0; t < 4; t++) {
                float p = __expf(acc_S[j][t] - mnew[t >> 1]);
                acc_S[j][t] = p;
                csum[t >> 1] += p;
            }
        #pragma unroll
        for (int o = 1; o <= 2; o <<= 1) {
            csum[0] += __shfl_xor_sync(0xffffffffu, csum[0], o);
            csum[1] += __shfl_xor_sync(0xffffffffu, csum[1], o);
        }
        lstate[0] = lstate[0] * scale[0] + csum[0];
        lstate[1] = lstate[1] * scale[1] + csum[1];
        mstate[0] = mnew[0];
        mstate[1] = mnew[1];
        #pragma unroll
        for (int j = 0; j < 8; j++)
            #pragma unroll
            for (int t = 0; t < 4; t++)
                acc_O[j][t] *= scale[t >> 1];

        // ---- P -> smem (warp-private rows, warp sync only) ----
        #pragma unroll
        for (int j = 0; j < 8; j++)
            #pragma unroll
            for (int t = 0; t < 4; t++) {
                int row = mrow + qr + ((t >= 2) ? 8 : 0);
                int col = j * 8 + r * 2 + (t & 1);
                sP[row * QSTR + col] = f2tf(acc_S[j][t]);
            }
        __syncwarp();

        // ---- O += P @ V  (contraction over keys: kk = key index) ----
        #pragma unroll
        for (int kk = 0; kk < BKC; kk += 8) {
            unsigned a[4] = { sP[(mrow + qr    ) * QSTR + kk + r    ],
                              sP[(mrow + qr + 8) * QSTR + kk + r    ],
                              sP[(mrow + qr    ) * QSTR + kk + r + 4],
                              sP[(mrow + qr + 8) * QSTR + kk + r + 4] };
            #pragma unroll
            for (int j = 0; j < 8; j++) {
                unsigned bb[2] = { sV[(kk + r    ) * QSTR + j * 8 + qr],
                                   sV[(kk + r + 4) * QSTR + j * 8 + qr] };
                MMA_TF32(acc_O[j], a, bb);
            }
        }
    }

    // ---- epilogue: normalize, store ----
    float inv[2] = { 1.f / lstate[0], 1.f / lstate[1] };
    #pragma unroll
    for (int j = 0; j < 8; j++)
        #pragma unroll
        for (int t = 0; t < 4; t++) {
            int row = q0 + mrow + qr + ((t >= 2) ? 8 : 0);
            int col = j * 8 + r * 2 + (t & 1);
            if (row < SEQ)
                O[((long long)b * SEQ + row) * DIM + h * HDIM + col] =
                    acc_O[j][t] * inv[t >> 1];
        }
}

// ---------------- reductions -------------------------------------------------
__device__ __forceinline__ float blockReduceSum(float v, volatile float* sh) {
    int lane = threadIdx.x & 31, w = threadIdx.x >> 5;
    #pragma unroll
    for (int o = 16; o; o >>= 1) v += __shfl_down_sync(0xffffffffu, v, o);
    if (lane == 0) sh[w] = v;
    __syncthreads();
    if (threadIdx.x < 32) {
        v = (threadIdx.x < 8) ? sh[threadIdx.x] : 0.f;
        #pragma unroll
        for (int o = 4; o; o >>= 1) v += __shfl_down_sync(0xffffffffu, v, o);
        if (lane == 0) sh[0] = v;
    }
    __syncthreads();
    return sh[0];
}

// ---------------- layernorm --------------------------------------------------
__global__ void __launch_bounds__(256)
layernorm_kernel(const float* __restrict__ X, const float* __restrict__ g,
                 const float* __restrict__ b, float* __restrict__ Y)
{
    long long row = blockIdx.x;
    const float* x = X + row * DIM;
    __shared__ float sh0[8], sh1[8];
    float v0 = x[threadIdx.x], v1 = x[threadIdx.x + 256], v2 = x[threadIdx.x + 512];
    float sum  = blockReduceSum(v0 + v1 + v2, sh0);
    float sum2 = blockReduceSum(v0 * v0 + v1 * v1 + v2 * v2, sh1);
    float m   = sum * (1.f / DIM);
    float var = sum2 * (1.f / DIM) - m * m;
    float inv = rsqrtf(var + 1e-5f);
    float* y = Y + row * DIM;
    #pragma unroll
    for (int i = 0; i < 3; i++) {
        int c = threadIdx.x + i * 256;
        float xv = (i == 0) ? v0 : (i == 1) ? v1 : v2;
        y[c] = (xv - m) * inv * g[c] + b[c];
    }
}

// ---------------- patchify ----------------------------------------------------
__global__ void __launch_bounds__(256)
patchify_kernel(const float* __restrict__ img)
{
    int idx = blockIdx.x * 256 + threadIdx.x;
    if (idx >= BATCH * NPATCH * PDIM) return;
    int pd = idx % PDIM;
    int t  = idx / PDIM;
    int patch = t % NPATCH;
    int b     = t / NPATCH;
    int c  = pd % 3;
    int pp = pd / 3;
    int p2 = pp % PSZ, p1 = pp / PSZ;
    int wx = patch % HP, hy = patch / HP;
    g_P[idx] = img[(((long long)b * 3 + c) * IMGH + hy * PSZ + p1) * IMGH + wx * PSZ + p2];
}

// ---------------- assemble: cls + pos add ------------------------------------
__global__ void __launch_bounds__(256)
assemble_kernel(const float* __restrict__ emb, const float* __restrict__ cls,
                const float* __restrict__ pos)
{
    int idx = blockIdx.x * 256 + threadIdx.x;
    if (idx >= BATCH * SEQ * DIM) return;
    int d = idx % DIM;
    int t = idx / DIM;
    int s = t % SEQ;
    int b = t / SEQ;
    float v;
    if (s == 0) v = cls[d] + pos[d];
    else        v = emb[((long long)b * NPATCH + (s - 1)) * DIM + d] + pos[(long long)s * DIM + d];
    g_X[idx] = v;
}

// ---------------- output: drop cls token -------------------------------------
__global__ void __launch_bounds__(256)
output_kernel(float* __restrict__ out)
{
    int idx = blockIdx.x * 256 + threadIdx.x;
    if (idx >= BATCH * NPATCH * DIM) return;
    int d = idx % DIM;
    int t = idx / DIM;
    int s = t % NPATCH;
    int b = t / NPATCH;
    out[idx] = g_X[((long long)b * SEQ + (s + 1)) * DIM + d];
}

// ---------------- host driver ------------------------------------------------
extern "C" void kernel_launch(void* const* d_in, const int* in_sizes, int n_in,
                              void* d_out, int out_size)
{
    const float* img   = (const float*)d_in[0];
    const float* pos   = (const float*)d_in[1];
    const float* cls   = (const float*)d_in[2];
    const float* pw    = (const float*)d_in[3];
    const float* pb    = (const float*)d_in[4];
    const float* ln1g  = (const float*)d_in[5];
    const float* ln1b  = (const float*)d_in[6];
    const float* qkvw  = (const float*)d_in[7];
    const float* outw  = (const float*)d_in[8];
    const float* outb  = (const float*)d_in[9];
    const float* ln2g  = (const float*)d_in[10];
    const float* ln2b  = (const float*)d_in[11];
    const float* ff1w  = (const float*)d_in[12];
    const float* ff1b  = (const float*)d_in[13];
    const float* ff2w  = (const float*)d_in[14];
    const float* ff2b  = (const float*)d_in[15];
    float* out = (float*)d_out;

    float *pX, *pY, *pQKV, *pO, *pH, *pP;
    cudaGetSymbolAddress((void**)&pX,   g_X);
    cudaGetSymbolAddress((void**)&pY,   g_Y);
    cudaGetSymbolAddress((void**)&pQKV, g_QKV);
    cudaGetSymbolAddress((void**)&pO,   g_O);
    cudaGetSymbolAddress((void**)&pH,   g_H);
    cudaGetSymbolAddress((void**)&pP,   g_P);

    const int Mfull = BATCH * SEQ;
    const int Mpat  = BATCH * NPATCH;

    const int FA_SMEM = (BQ + BKC + BKC + BQ) * QSTR * 4;   // 104448 B
    cudaFuncSetAttribute((const void*)flash_attn_kernel,
                         cudaFuncAttributeMaxDynamicSharedMemorySize, FA_SMEM);

    auto grid = [](int M, int N, int BMv, int BNv, int Z) {
        return dim3((N + BNv - 1) / BNv, (M + BMv - 1) / BMv, Z);
    };

    // 1) patchify + patch embed + assemble
    patchify_kernel<<<(BATCH * NPATCH * PDIM + 255) / 256, 256>>>(img);
    gemm_tc<128,128,32,2,4><<<grid(Mpat, DIM, 128, 128, 1), 256>>>(
        pP, PDIM, 0, 0, 1,  pw, DIM, 0, 0, 0,  pb,
        pY, DIM, 0, 0,  Mpat, DIM, PDIM, 0);
    assemble_kernel<<<(BATCH * SEQ * DIM + 255) / 256, 256>>>(pY, cls, pos);

    // 2) transformer layers
    for (int l = 0; l < DEPTH; l++) {
        const float* wqkv = qkvw + (long long)l * DIM * 3 * DIM;
        const float* wo   = outw + (long long)l * DIM * DIM;
        const float* bo   = outb + (long long)l * DIM;
        const float* w1   = ff1w + (long long)l * DIM * MLPD;
        const float* b1   = ff1b + (long long)l * MLPD;
        const float* w2   = ff2w + (long long)l * MLPD * DIM;
        const float* b2   = ff2b + (long long)l * DIM;

        layernorm_kernel<<<Mfull, 256>>>(pX, ln1g + (long long)l * DIM,
                                         ln1b + (long long)l * DIM, pY);
        // QKV = Y @ Wqkv
        gemm_tc<128,128,32,2,4><<<grid(Mfull, 3 * DIM, 128, 128, 1), 256>>>(
            pY, DIM, 0, 0, 1,  wqkv, 3 * DIM, 0, 0, 0,  nullptr,
            pQKV, 3 * DIM, 0, 0,  Mfull, 3 * DIM, DIM, 0);
        // fused attention: QK^T -> softmax -> PV, no score tensor
        {
            dim3 g(1, (SEQ + BQ - 1) / BQ, BATCH * HEADS);
            flash_attn_kernel<<<g, 256, FA_SMEM>>>(pQKV, pO);
        }
        // X += O @ Wo + bo
        gemm_tc<128,128,32,2,4><<<grid(Mfull, DIM, 128, 128, 1), 256>>>(
            pO, DIM, 0, 0, 1,  wo, DIM, 0, 0, 0,  bo,
            pX, DIM, 0, 0,  Mfull, DIM, DIM, 2);
        layernorm_kernel<<<Mfull, 256>>>(pX, ln2g + (long long)l * DIM,
                                         ln2b + (long long)l * DIM, pY);
        // H = gelu(Y @ W1 + b1)
        gemm_tc<128,128,32,2,4><<<grid(Mfull, MLPD, 128, 128, 1), 256>>>(
            pY, DIM, 0, 0, 1,  w1, MLPD, 0, 0, 0,  b1,
            pH, MLPD, 0, 0,  Mfull, MLPD, DIM, 1);
        // X += H @ W2 + b2
        gemm_tc<128,128,32,2,4><<<grid(Mfull, DIM, 128, 128, 1), 256>>>(
            pH, MLPD, 0, 0, 1,  w2, DIM, 0, 0, 0,  b2,
            pX, DIM, 0, 0,  Mfull, DIM, MLPD, 2);
    }

    // 3) drop cls token -> output
    output_kernel<<<(BATCH * NPATCH * DIM + 255) / 256, 256>>>(out);
}